// round 3
// baseline (speedup 1.0000x reference)
#include <cuda_runtime.h>
#include <math.h>

// Problem shapes (fixed by setup_inputs)
#define C_    16
#define H_    256
#define W_    512
#define ND_   32
#define HW_   (H_ * W_)          // 131072
#define NDHW_ (ND_ * HW_)        // 4194304
#define BASELINE_ 0.24f

// ---------------------------------------------------------------------------
// Kernel 1: reference half — out[c, d, h, w] = x[c, h, w] for c in [0,16)
// float4 vectorized broadcast over the 32 disparities.
// ---------------------------------------------------------------------------
__global__ void ref_broadcast_kernel(const float4* __restrict__ x4,
                                     float4* __restrict__ out4) {
    int i = blockIdx.x * blockDim.x + threadIdx.x;   // index over C*H*W/4
    if (i >= (C_ * HW_) / 4) return;

    float4 v = x4[i];

    // i = c*(H*W/4) + h*(W/4) + w4
    int w4 = i & (W_ / 4 - 1);          // 0..127
    int h  = (i >> 7) & (H_ - 1);       // 0..255
    int c  = i >> 15;                   // 0..15

    // out (in float4 units): c*NDHW/4 + d*HW/4 + h*W/4 + w4
    long base = (long)c * (NDHW_ / 4) + (long)h * (W_ / 4) + w4;
#pragma unroll 8
    for (int d = 0; d < ND_; ++d) {
        out4[base + (long)d * (HW_ / 4)] = v;
    }
}

// ---------------------------------------------------------------------------
// Kernel 2: warped half — out[16+c, d, h, w] = bilinear(y[c], u(w), v(h,d))
// One thread per (d,h,w); weights/offsets hoisted out of channel loop.
// ---------------------------------------------------------------------------
__global__ void warp_sample_kernel(const float* __restrict__ y,
                                   const float* __restrict__ depth,
                                   float* __restrict__ out) {
    int tid = blockIdx.x * blockDim.x + threadIdx.x;  // over ND*H*W
    if (tid >= NDHW_) return;

    int w = tid & (W_ - 1);
    int h = (tid >> 9) & (H_ - 1);
    int d = tid >> 17;

    const float PI = 3.14159265358979323846f;

    // theta per row (equirectangular, pixel-centered)
    float theta = ((float)h + 0.5f) * (PI / (float)H_) - PI * 0.5f;
    float s, c;
    sincosf(theta, &s, &c);

    float dep = depth[tid];

    // dtheta_vertical -> pixel rows
    float dth = atanf((dep * s + BASELINE_) / (dep * c)) - theta;
    float d_v = dth * ((float)H_ / PI);

    // torch zeroes non-finite entries of (v + d_v)
    float y_px = isfinite(d_v) ? ((float)h + d_v) : 0.0f;

    // normalize then unnormalize exactly like the reference (align_corners=False)
    float gx = (float)w / ((W_ - 1.0f) * 0.5f) - 1.0f;
    float gy = y_px     / ((H_ - 1.0f) * 0.5f) - 1.0f;
    float ix = ((gx + 1.0f) * (float)W_ - 1.0f) * 0.5f;
    float iy = ((gy + 1.0f) * (float)H_ - 1.0f) * 0.5f;

    float fx0 = floorf(ix);
    float fy0 = floorf(iy);
    float wx1 = ix - fx0;
    float wy1 = iy - fy0;
    float wx0 = 1.0f - wx1;
    float wy0 = 1.0f - wy1;

    int x0 = (int)fx0;
    int y0 = (int)fy0;
    int x1 = x0 + 1;
    int y1 = y0 + 1;

    bool vx0 = (x0 >= 0) & (x0 < W_);
    bool vx1 = (x1 >= 0) & (x1 < W_);
    bool vy0 = (y0 >= 0) & (y0 < H_);
    bool vy1 = (y1 >= 0) & (y1 < H_);

    float w00 = wx0 * wy0 * (float)(vx0 & vy0);
    float w10 = wx1 * wy0 * (float)(vx1 & vy0);
    float w01 = wx0 * wy1 * (float)(vx0 & vy1);
    float w11 = wx1 * wy1 * (float)(vx1 & vy1);

    int cx0 = min(max(x0, 0), W_ - 1);
    int cx1 = min(max(x1, 0), W_ - 1);
    int cy0 = min(max(y0, 0), H_ - 1);
    int cy1 = min(max(y1, 0), H_ - 1);

    int o00 = cy0 * W_ + cx0;
    int o10 = cy0 * W_ + cx1;
    int o01 = cy1 * W_ + cx0;
    int o11 = cy1 * W_ + cx1;

    // out offset for channel (16+c): (16+c)*NDHW + d*HW + h*W + w
    long obase = 16L * NDHW_ + (long)d * HW_ + (long)h * W_ + w;

#pragma unroll
    for (int ch = 0; ch < C_; ++ch) {
        const float* yc = y + ch * HW_;
        float v = w00 * __ldg(yc + o00)
                + w10 * __ldg(yc + o10)
                + w01 * __ldg(yc + o01)
                + w11 * __ldg(yc + o11);
        out[obase + (long)ch * NDHW_] = v;
    }
}

extern "C" void kernel_launch(void* const* d_in, const int* in_sizes, int n_in,
                              void* d_out, int out_size) {
    const float* x     = (const float*)d_in[0];
    const float* y     = (const float*)d_in[1];
    const float* depth = (const float*)d_in[2];
    float* out = (float*)d_out;

    {
        int total = (C_ * HW_) / 4;          // 524288 float4 elems
        int threads = 256;
        int blocks = (total + threads - 1) / threads;
        ref_broadcast_kernel<<<blocks, threads>>>((const float4*)x, (float4*)out);
    }
    {
        int total = NDHW_;                   // 4194304
        int threads = 256;
        int blocks = (total + threads - 1) / threads;
        warp_sample_kernel<<<blocks, threads>>>(y, depth, out);
    }
}